// round 1
// baseline (speedup 1.0000x reference)
#include <cuda_runtime.h>

// Unpool_LS: x0 [8,256,256,64] f32, x1 [8,128,128,64] f32, pool 2x2.
// Outputs (flattened, concatenated): out0 [8,256,256,64], repl [8,128,128,64],
// out3 [8,256,256,64].
//
// Per 2x2 block (4 values v0..v3, row-major within block) + pooled value x:
//   stable descending ranks r_j
//   sorted desc s0>=s1>=s2>=s3 (min/max network)
//   cs_j = x + sum_{i<=j} s_i ; avg_j = cs_j/(j+2)
//   repl = max avg (first max -> k) ; frac = (k+1)/(k+2)
//   mask_j = r_j <= k ; out0_j = mask ? repl : v_j ; out3_j = mask ? frac : 1

#define NB   8
#define NH   256
#define NW   256
#define NC   64
#define NHH  128
#define NWW  128

#define N0 (NB * NH * NW * NC)      // 33554432
#define N1 (NB * NHH * NWW * NC)    // 1048576

__device__ __forceinline__ void solve1(
    float v0, float v1, float v2, float v3, float xv,
    float& o0, float& o1, float& o2, float& o3,
    float& rp,
    float& t0, float& t1, float& t2, float& t3)
{
    // Stable descending ranks (permutation of {0,1,2,3}).
    int r0 = (v1 >  v0) + (v2 >  v0) + (v3 >  v0);
    int r1 = (v0 >= v1) + (v2 >  v1) + (v3 >  v1);
    int r2 = (v0 >= v2) + (v1 >= v2) + (v3 >  v2);
    int r3 = (v0 >= v3) + (v1 >= v3) + (v2 >= v3);

    // Sort descending via min/max network (ties don't affect values).
    float lo01 = fminf(v0, v1), hi01 = fmaxf(v0, v1);
    float lo23 = fminf(v2, v3), hi23 = fmaxf(v2, v3);
    float s0 = fmaxf(hi01, hi23);
    float s3 = fminf(lo01, lo23);
    float m1 = fminf(hi01, hi23);
    float m2 = fmaxf(lo01, lo23);
    float s1 = fmaxf(m1, m2);
    float s2 = fminf(m1, m2);

    float cs0 = s0 + xv;
    float cs1 = cs0 + s1;
    float cs2 = cs1 + s2;
    float cs3 = cs2 + s3;

    float a0 = cs0 * 0.5f;
    float a1 = cs1 * (1.0f / 3.0f);
    float a2 = cs2 * 0.25f;
    float a3 = cs3 * 0.2f;

    // First-max argmax.
    float best = a0; int k = 0;
    if (a1 > best) { best = a1; k = 1; }
    if (a2 > best) { best = a2; k = 2; }
    if (a3 > best) { best = a3; k = 3; }

    rp = best;
    float frac = (k == 0) ? 0.5f
               : (k == 1) ? (2.0f / 3.0f)
               : (k == 2) ? 0.75f
               : 0.8f;

    o0 = (r0 <= k) ? best : v0;
    o1 = (r1 <= k) ? best : v1;
    o2 = (r2 <= k) ? best : v2;
    o3 = (r3 <= k) ? best : v3;
    t0 = (r0 <= k) ? frac : 1.0f;
    t1 = (r1 <= k) ? frac : 1.0f;
    t2 = (r2 <= k) ? frac : 1.0f;
    t3 = (r3 <= k) ? frac : 1.0f;
}

__global__ __launch_bounds__(256) void unpool_ls_kernel(
    const float* __restrict__ x0,
    const float* __restrict__ x1,
    float* __restrict__ out)
{
    int t = blockIdx.x * blockDim.x + threadIdx.x;
    // t in [0, NB*NHH*NWW*(NC/4)) = 2,097,152
    int c4 = t & 15;             // 16 channel-quads
    int w  = (t >> 4) & (NWW - 1);
    int h  = (t >> 11) & (NHH - 1);
    int b  = t >> 18;

    int c = c4 * 4;

    // x0 / out0 / out3 base for (b, 2h, 2w, c)
    long base = (((long)(b * NH + 2 * h)) * NW + 2 * w) * NC + c;
    const long dW  = NC;          // +1 in x direction
    const long dH  = (long)NW * NC; // +1 in y direction

    float4 q00 = *(const float4*)(x0 + base);
    float4 q01 = *(const float4*)(x0 + base + dW);
    float4 q10 = *(const float4*)(x0 + base + dH);
    float4 q11 = *(const float4*)(x0 + base + dH + dW);

    long pbase = (((long)(b * NHH + h)) * NWW + w) * NC + c;
    float4 p = *(const float4*)(x1 + pbase);

    float4 o00, o01, o10, o11, rp, t00, t01, t10, t11;

    solve1(q00.x, q01.x, q10.x, q11.x, p.x,
           o00.x, o01.x, o10.x, o11.x, rp.x, t00.x, t01.x, t10.x, t11.x);
    solve1(q00.y, q01.y, q10.y, q11.y, p.y,
           o00.y, o01.y, o10.y, o11.y, rp.y, t00.y, t01.y, t10.y, t11.y);
    solve1(q00.z, q01.z, q10.z, q11.z, p.z,
           o00.z, o01.z, o10.z, o11.z, rp.z, t00.z, t01.z, t10.z, t11.z);
    solve1(q00.w, q01.w, q10.w, q11.w, p.w,
           o00.w, o01.w, o10.w, o11.w, rp.w, t00.w, t01.w, t10.w, t11.w);

    float* out0 = out;
    float* orep = out + N0;
    float* out3 = out + N0 + N1;

    *(float4*)(out0 + base)           = o00;
    *(float4*)(out0 + base + dW)      = o01;
    *(float4*)(out0 + base + dH)      = o10;
    *(float4*)(out0 + base + dH + dW) = o11;

    *(float4*)(orep + pbase) = rp;

    *(float4*)(out3 + base)           = t00;
    *(float4*)(out3 + base + dW)      = t01;
    *(float4*)(out3 + base + dH)      = t10;
    *(float4*)(out3 + base + dH + dW) = t11;
}

extern "C" void kernel_launch(void* const* d_in, const int* in_sizes, int n_in,
                              void* d_out, int out_size) {
    const float* x0 = (const float*)d_in[0];
    const float* x1 = (const float*)d_in[1];
    float* out = (float*)d_out;

    const int threads = NB * NHH * NWW * (NC / 4);  // 2,097,152
    unpool_ls_kernel<<<threads / 256, 256>>>(x0, x1, out);
}